// round 8
// baseline (speedup 1.0000x reference)
#include <cuda_runtime.h>
#include <cuda_bf16.h>
#include <cstdint>

// ---------------------------------------------------------------------------
// ShiftedWindowAttention — round 8: GEMM warp tile 32x64 (128B ldsm per MMA),
// hi/lo interleaved SMEM rows, cp.async double-buffered K16 chunks, 2 CTAs/SM.
// ---------------------------------------------------------------------------

#define NWIN   2048
#define NTOK   131072
#define HEADS  8
#define HD     32
#define WS2    64
#define DIM    256
#define ATT_SCALE 0.17677669529663687f

// ---------------- scratch ---------------------------------------------------
__device__ __nv_bfloat16 g_wqh[768 * DIM];
__device__ __nv_bfloat16 g_wql[768 * DIM];
__device__ __nv_bfloat16 g_woh[DIM * DIM];
__device__ __nv_bfloat16 g_wol[DIM * DIM];
__device__ __nv_bfloat16 g_qh[NWIN * HEADS * WS2 * HD];
__device__ __nv_bfloat16 g_ql[NWIN * HEADS * WS2 * HD];
__device__ __nv_bfloat16 g_kh[NWIN * HEADS * WS2 * HD];
__device__ __nv_bfloat16 g_kl[NWIN * HEADS * WS2 * HD];
__device__ __nv_bfloat16 g_vh[NWIN * HEADS * WS2 * HD];
__device__ __nv_bfloat16 g_vl[NWIN * HEADS * WS2 * HD];
__device__ __nv_bfloat16 g_ath[NTOK * DIM];
__device__ __nv_bfloat16 g_atl[NTOK * DIM];

// ---------------- helpers ---------------------------------------------------
__device__ __forceinline__ uint32_t smem_u32(const void* p) {
    uint32_t a;
    asm("{ .reg .u64 t; cvta.to.shared.u64 t, %1; cvt.u32.u64 %0, t; }"
        : "=r"(a) : "l"(p));
    return a;
}
__device__ __forceinline__ void ldsm4(uint32_t& r0, uint32_t& r1,
                                      uint32_t& r2, uint32_t& r3, uint32_t a) {
    asm volatile("ldmatrix.sync.aligned.m8n8.x4.shared.b16 {%0,%1,%2,%3}, [%4];"
                 : "=r"(r0), "=r"(r1), "=r"(r2), "=r"(r3) : "r"(a));
}
__device__ __forceinline__ void ldsm4t(uint32_t& r0, uint32_t& r1,
                                       uint32_t& r2, uint32_t& r3, uint32_t a) {
    asm volatile("ldmatrix.sync.aligned.m8n8.x4.trans.shared.b16 {%0,%1,%2,%3}, [%4];"
                 : "=r"(r0), "=r"(r1), "=r"(r2), "=r"(r3) : "r"(a));
}
#define MMA16816(c, a, b)                                                  \
    asm volatile("mma.sync.aligned.m16n8k16.row.col.f32.bf16.bf16.f32 "    \
        "{%0,%1,%2,%3}, {%4,%5,%6,%7}, {%8,%9}, {%0,%1,%2,%3};"            \
        : "+f"((c)[0]), "+f"((c)[1]), "+f"((c)[2]), "+f"((c)[3])           \
        : "r"((a)[0]), "r"((a)[1]), "r"((a)[2]), "r"((a)[3]),              \
          "r"((b)[0]), "r"((b)[1]))

#define CP_ASYNC16(dst, src) \
    asm volatile("cp.async.cg.shared.global [%0], [%1], 16;" \
                 :: "r"(dst), "l"(src) : "memory")
#define CP_COMMIT() asm volatile("cp.async.commit_group;" ::: "memory")
#define CP_WAIT0()  asm volatile("cp.async.wait_group 0;" ::: "memory")

__device__ __forceinline__ void split2(float x, float y,
                                       uint32_t& hi, uint32_t& lo) {
    __nv_bfloat16 xh = __float2bfloat16_rn(x);
    __nv_bfloat16 yh = __float2bfloat16_rn(y);
    __nv_bfloat16 xl = __float2bfloat16_rn(x - __bfloat162float(xh));
    __nv_bfloat16 yl = __float2bfloat16_rn(y - __bfloat162float(yh));
    __nv_bfloat162 h2 = __halves2bfloat162(xh, yh);
    __nv_bfloat162 l2 = __halves2bfloat162(xl, yl);
    hi = *(uint32_t*)&h2;
    lo = *(uint32_t*)&l2;
}

// ---------------- index map (roll -4,-4 + window split) --------------------
__device__ __forceinline__ int src_offset(int R) {
    int w = R >> 6, t = R & 63;
    int b = w >> 6, widx = w & 63;
    int wy = widx >> 3, wx = widx & 7;
    int ty = t >> 3, tx = t & 7;
    int ys = ((wy << 3) + ty + 4) & 63;
    int xs = ((wx << 3) + tx + 4) & 63;
    return ((b << 12) + (ys << 6) + xs) * DIM;
}

// ---------------- fp32 -> bf16 hi/lo split (weights only) ------------------
__global__ __launch_bounds__(256) void conv_split(
    const float* __restrict__ src, __nv_bfloat16* __restrict__ hp,
    __nv_bfloat16* __restrict__ lp, int n4)
{
    int i = blockIdx.x * 256 + threadIdx.x;
    if (i >= n4) return;
    float4 v = ((const float4*)src)[i];
    uint32_t h0, l0, h1, l1;
    split2(v.x, v.y, h0, l0);
    split2(v.z, v.w, h1, l1);
    ((uint32_t*)hp)[2 * i + 0] = h0;
    ((uint32_t*)hp)[2 * i + 1] = h1;
    ((uint32_t*)lp)[2 * i + 0] = l0;
    ((uint32_t*)lp)[2 * i + 1] = l1;
}

// ---------------------------------------------------------------------------
// HMMA GEMM. CTA: M=64, N-tile 256, 8 warps of 32x64 (2M x 4N).
// K chunks of 16 with hi/lo interleaved per row; cp.async double buffer.
// A smem: 64 rows x 520 (cols 0-255 hi, 256-511 lo)  = 65 KB
// B smem buffer: 256 rows x 40 (16 hi | 16 lo)       = 20 KB x2
// MODE 0: qkv (3 n-tiles = q,k,v), A = fp32 x split on the fly.
// MODE 1: out-proj (1 n-tile),     A = g_ath/g_atl.
// ---------------------------------------------------------------------------
#define A_STR   520
#define A_OFF   1024
#define A_SZ    66560
#define B_STR   40
#define B_OFF   (A_OFF + A_SZ)              // 67584
#define B_BUF   20480
#define SMEM_SZ (B_OFF + 2 * B_BUF)         // 108544

template <int MODE>
__global__ __launch_bounds__(256, 2) void gemm_tc(
    const float* __restrict__ Af,
    const __nv_bfloat16* __restrict__ Ah, const __nv_bfloat16* __restrict__ Al,
    const __nv_bfloat16* __restrict__ Bh, const __nv_bfloat16* __restrict__ Bl,
    const float* __restrict__ bias, float* __restrict__ outp)
{
    constexpr int NT  = (MODE == 0) ? 3 : 1;
    constexpr int TOT = NT * 16;             // K16 chunks
    extern __shared__ char smem[];
    const uint32_t sbase = smem_u32(smem);
    const int tid  = threadIdx.x;
    const int wid  = tid >> 5;
    const int lane = tid & 31;
    const int bx   = blockIdx.x;
    const int m0 = (wid & 1) * 32;
    const int n0 = (wid >> 1) * 64;

    int* rowOff = (int*)smem;
    if (tid < 64) {
        int R = bx * 64 + tid;
        rowOff[tid] = (MODE == 0) ? src_offset(R) : R * DIM;
    }
    __syncthreads();

    // ---- A tile into SMEM (hi cols 0-255, lo cols 256-511, stride 520) ----
    if (MODE == 0) {
#pragma unroll
        for (int i = 0; i < 16; i++) {
            int idx = tid + i * 256;          // 4096 float4
            int u = idx & 63;                 // float4 within row
            int r = idx >> 6;
            float4 v = *(const float4*)(Af + rowOff[r] + u * 4);
            uint32_t h0, l0, h1, l1;
            split2(v.x, v.y, h0, l0);
            split2(v.z, v.w, h1, l1);
            char* base = smem + A_OFF + (r * A_STR + u * 4) * 2;
            *(uint2*)base = make_uint2(h0, h1);
            *(uint2*)(base + 512) = make_uint2(l0, l1);   // +256 elems
        }
    } else {
#pragma unroll
        for (int i = 0; i < 16; i++) {
            int idx = tid + i * 256;          // 4096 uint4
            int hl = idx >> 11;
            int r  = (idx >> 5) & 63;
            int u  = idx & 31;
            const __nv_bfloat16* s = (hl ? Al : Ah) + rowOff[r] + u * 8;
            uint4 v = *(const uint4*)s;
            *(uint4*)(smem + A_OFF + (r * A_STR + hl * 256 + u * 8) * 2) = v;
        }
    }

    // ---- B chunk loader via cp.async: chunk gg -> buffer b ----
    auto loadB = [&](int gg, int b) {
        const int nb = (gg >> 4) * 256;
        const int kk = (gg & 15) * 16;
#pragma unroll
        for (int i = 0; i < 4; i++) {
            int idx = tid + i * 256;          // 1024 x 16B
            int hl = idx >> 9, r = (idx >> 1) & 255, u = idx & 1;
            const __nv_bfloat16* s = (hl ? Bl : Bh) + (nb + r) * DIM + kk + u * 8;
            uint32_t d = sbase + B_OFF + b * B_BUF + (r * B_STR + hl * 16 + u * 8) * 2;
            CP_ASYNC16(d, s);
        }
        CP_COMMIT();
    };

    loadB(0, 0);
    CP_WAIT0();
    __syncthreads();

    const int a_row = lane & 15;
    const int a_col = (lane >> 4) * 8;
    const int b_row = (lane & 7) + ((lane >> 4) << 3);
    const int b_col = ((lane >> 3) & 1) * 8;
    const uint32_t aAddr = sbase + A_OFF + ((m0 + a_row) * A_STR + a_col) * 2;

    float acc[2][8][4];
#pragma unroll
    for (int mf = 0; mf < 2; mf++)
#pragma unroll
        for (int nf = 0; nf < 8; nf++)
#pragma unroll
            for (int q = 0; q < 4; q++) acc[mf][nf][q] = 0.f;

#pragma unroll 1
    for (int g = 0; g < TOT; g++) {
        const int kk = (g & 15) * 16;

        if (g + 1 < TOT) loadB(g + 1, (g + 1) & 1);

        // ---- compute chunk g ----
        const uint32_t bBase = sbase + B_OFF + (g & 1) * B_BUF;
        uint32_t ah[2][4], al[2][4];
#pragma unroll
        for (int mf = 0; mf < 2; mf++) {
            uint32_t a = aAddr + (mf * 16 * A_STR + kk) * 2;
            ldsm4(ah[mf][0], ah[mf][1], ah[mf][2], ah[mf][3], a);
            ldsm4(al[mf][0], al[mf][1], al[mf][2], al[mf][3], a + 512);
        }
#pragma unroll
        for (int w2 = 0; w2 < 2; w2++) {      // two waves of 4 nf
            uint32_t bh[4][2], bl[4][2];
#pragma unroll
            for (int nb2 = 0; nb2 < 2; nb2++) {
                uint32_t ba = bBase +
                    ((n0 + w2 * 32 + nb2 * 16 + b_row) * B_STR + b_col) * 2;
                ldsm4(bh[2 * nb2][0], bh[2 * nb2][1],
                      bh[2 * nb2 + 1][0], bh[2 * nb2 + 1][1], ba);
                ldsm4(bl[2 * nb2][0], bl[2 * nb2][1],
                      bl[2 * nb2 + 1][0], bl[2 * nb2 + 1][1], ba + 32);
            }
#pragma unroll
            for (int mf = 0; mf < 2; mf++)
#pragma unroll
                for (int nf = 0; nf < 4; nf++) {
                    MMA16816(acc[mf][w2 * 4 + nf], ah[mf], bh[nf]);
                    MMA16816(acc[mf][w2 * 4 + nf], ah[mf], bl[nf]);
                    MMA16816(acc[mf][w2 * 4 + nf], al[mf], bh[nf]);
                }
        }

        // ---- epilogue at end of each n-tile ----
        if ((g & 15) == 15) {
            const int nt = g >> 4;
            const int erow = lane >> 2;
            const int ecol = (lane & 3) * 2;
            if (MODE == 0) {
                __nv_bfloat16* dh = (nt == 0) ? g_qh : (nt == 1) ? g_kh : g_vh;
                __nv_bfloat16* dl = (nt == 0) ? g_ql : (nt == 1) ? g_kl : g_vl;
#pragma unroll
                for (int mf = 0; mf < 2; mf++) {
                    int R0 = bx * 64 + m0 + mf * 16 + erow;
                    int w0 = R0 >> 6, t0 = R0 & 63;
                    int R1 = R0 + 8;
                    int w1 = R1 >> 6, t1 = R1 & 63;
#pragma unroll
                    for (int nf = 0; nf < 8; nf++) {
                        int rem = n0 + nf * 8 + ecol;        // 0..255
                        int jg = nt * 256 + rem;
                        float bx0 = __ldg(&bias[jg]);
                        float bx1 = __ldg(&bias[jg + 1]);
                        int h = rem >> 5, d = rem & 31;
                        uint32_t hi, lo;
                        int off0 = (((w0 << 3) + h) * WS2 + t0) * HD + d;
                        split2(acc[mf][nf][0] + bx0, acc[mf][nf][1] + bx1, hi, lo);
                        *(uint32_t*)&dh[off0] = hi;
                        *(uint32_t*)&dl[off0] = lo;
                        int off1 = (((w1 << 3) + h) * WS2 + t1) * HD + d;
                        split2(acc[mf][nf][2] + bx0, acc[mf][nf][3] + bx1, hi, lo);
                        *(uint32_t*)&dh[off1] = hi;
                        *(uint32_t*)&dl[off1] = lo;
                    }
                }
            } else {
#pragma unroll
                for (int mf = 0; mf < 2; mf++) {
                    int R0 = bx * 64 + m0 + mf * 16 + erow;
                    int so0 = src_offset(R0);
                    int so1 = src_offset(R0 + 8);
#pragma unroll
                    for (int nf = 0; nf < 8; nf++) {
                        int jg = n0 + nf * 8 + ecol;
                        float bx0 = __ldg(&bias[jg]);
                        float bx1 = __ldg(&bias[jg + 1]);
                        *(float2*)&outp[so0 + jg] =
                            make_float2(acc[mf][nf][0] + bx0, acc[mf][nf][1] + bx1);
                        *(float2*)&outp[so1 + jg] =
                            make_float2(acc[mf][nf][2] + bx0, acc[mf][nf][3] + bx1);
                    }
                }
            }
            if (g + 1 < TOT) {
#pragma unroll
                for (int mf = 0; mf < 2; mf++)
#pragma unroll
                    for (int nf = 0; nf < 8; nf++)
#pragma unroll
                        for (int q = 0; q < 4; q++) acc[mf][nf][q] = 0.f;
            }
        }

        CP_WAIT0();
        __syncthreads();
    }
}

// ---------------------------------------------------------------------------
// HMMA attention (unchanged from round 7).
// ---------------------------------------------------------------------------
#define QSTR 40
#define T_SZ 10240
#define AQH 0
#define AQL (1 * T_SZ)
#define AKH (2 * T_SZ)
#define AKL (3 * T_SZ)
#define AVH (4 * T_SZ)
#define AVL (5 * T_SZ)
#define APS (6 * T_SZ)
#define ARG (APS + 1800)
#define ATT_SMEM (ARG + 256)

__global__ __launch_bounds__(128) void attn_mma(const float* __restrict__ pos_enc)
{
    extern __shared__ char smem[];
    const uint32_t sbase = smem_u32(smem);
    const int w    = blockIdx.x;
    const int hp   = blockIdx.y;
    const int tid  = threadIdx.x;
    const int wid  = tid >> 5;
    const int lane = tid & 31;
    const int hl2  = wid >> 1;
    const int m0   = (wid & 1) * 32;

    {
        const __nv_bfloat16* srcs[6] = {g_qh, g_ql, g_kh, g_kl, g_vh, g_vl};
#pragma unroll
        for (int i = 0; i < 24; i++) {
            int idx = tid + i * 128;
            int u = idx & 3, r = (idx >> 2) & 63, hh = (idx >> 8) & 1, tz = idx >> 9;
            const __nv_bfloat16* s = srcs[tz] +
                ((((w << 3) + (hp << 1) + hh) * WS2 + r) * HD) + u * 8;
            uint4 v = *(const uint4*)s;
            *(uint4*)(smem + tz * T_SZ + ((hh * 64 + r) * QSTR + u * 8) * 2) = v;
        }
        float* psf = (float*)(smem + APS);
        for (int i = tid; i < 450; i += 128)
            psf[i] = pos_enc[(hp * 2) * 225 + i];
        int* rgp = (int*)(smem + ARG);
        if (tid < 64) {
            int widx = w & 63;
            int wy = widx >> 3, wx = widx & 7;
            int ry = (wy < 7) ? 0 : ((tid >> 3) < 4 ? 1 : 2);
            int rx = (wx < 7) ? 0 : ((tid & 7) < 4 ? 1 : 2);
            rgp[tid] = ry * 3 + rx;
        }
    }
    __syncthreads();

    const float* ps = (const float*)(smem + APS) + hl2 * 225;
    const int* rg = (const int*)(smem + ARG);

    float s[2][8][4];
#pragma unroll
    for (int mf = 0; mf < 2; mf++)
#pragma unroll
        for (int nf = 0; nf < 8; nf++)
#pragma unroll
            for (int q = 0; q < 4; q++) s[mf][nf][q] = 0.f;

    const int a_row = lane & 15;
    const int a_col = (lane >> 4) * 8;
    const int b_row = (lane & 7) + ((lane >> 4) << 3);
    const int b_col = ((lane >> 3) & 1) * 8;
    const uint32_t qA = sbase + AQH + ((hl2 * 64 + m0 + a_row) * QSTR + a_col) * 2;
    const uint32_t kB = sbase + AKH + ((hl2 * 64 + b_row) * QSTR + b_col) * 2;

#pragma unroll
    for (int ks = 0; ks < 2; ks++) {
        uint32_t ah[2][4], al[2][4], bh[8][2], bl[8][2];
#pragma unroll
        for (int mf = 0; mf < 2; mf++) {
            uint32_t a = qA + (mf * 16 * QSTR + ks * 16) * 2;
            ldsm4(ah[mf][0], ah[mf][1], ah[mf][2], ah[mf][3], a);
            ldsm4(al[mf][0], al[mf][1], al[mf][2], al[mf][3], a + T_SZ);
        }
#pragma unroll
        for (int nf2 = 0; nf2 < 4; nf2++) {
            uint32_t b = kB + (nf2 * 16 * QSTR + ks * 16) * 2;
            ldsm4(bh[2 * nf2][0], bh[2 * nf2][1],
                  bh[2 * nf2 + 1][0], bh[2 * nf2 + 1][1], b);
            ldsm4(bl[2 * nf2][0], bl[2 * nf2][1],
                  bl[2 * nf2 + 1][0], bl[2 * nf2 + 1][1], b + T_SZ);
        }
#pragma unroll
        for (int mf = 0; mf < 2; mf++)
#pragma unroll
            for (int nf = 0; nf < 8; nf++) {
                MMA16816(s[mf][nf], ah[mf], bh[nf]);
                MMA16816(s[mf][nf], ah[mf], bl[nf]);
                MMA16816(s[mf][nf], al[mf], bh[nf]);
            }
    }

    const int rowl = lane >> 2;
    const int colb = (lane & 3) * 2;
#pragma unroll
    for (int mf = 0; mf < 2; mf++) {
        int t1a = m0 + mf * 16 + rowl, t1b = t1a + 8;
        int y1a = t1a >> 3, x1a = t1a & 7;
        int y1b = t1b >> 3, x1b = t1b & 7;
        int rga = rg[t1a], rgb = rg[t1b];
        float mxa = -1e30f, mxb = -1e30f;
#pragma unroll
        for (int nf = 0; nf < 8; nf++)
#pragma unroll
            for (int e = 0; e < 2; e++) {
                int t2 = nf * 8 + colb + e;
                int y2 = t2 >> 3, x2 = t2 & 7;
                int rgc = rg[t2];
                float va = fmaf(s[mf][nf][e], ATT_SCALE,
                                ps[(y1a - y2 + 7) * 15 + (x1a - x2 + 7)]);
                float vb = fmaf(s[mf][nf][2 + e], ATT_SCALE,
                                ps[(y1b - y2 + 7) * 15 + (x1b - x2 + 7)]);
                if (rgc != rga) va = -1e30f;
                if (rgc != rgb) vb = -1e30f;
                s[mf][nf][e] = va;
                s[mf][nf][2 + e] = vb;
                mxa = fmaxf(mxa, va);
                mxb = fmaxf(mxb, vb);
            }
        mxa = fmaxf(mxa, __shfl_xor_sync(0xffffffffu, mxa, 1));
        mxa = fmaxf(mxa, __shfl_xor_sync(0xffffffffu, mxa, 2));
        mxb = fmaxf(mxb, __shfl_xor_sync(0xffffffffu, mxb, 1));
        mxb = fmaxf(mxb, __shfl_xor_sync(0xffffffffu, mxb, 2));
        float sma = 0.f, smb = 0.f;
#pragma unroll
        for (int nf = 0; nf < 8; nf++)
#pragma unroll
            for (int e = 0; e < 2; e++) {
                float ea = __expf(s[mf][nf][e] - mxa);
                float eb = __expf(s[mf][nf][2 + e] - mxb);
                s[mf][nf][e] = ea;
                s[mf][nf][2 + e] = eb;
                sma += ea;
                smb += eb;
            }
        sma += __shfl_xor_sync(0xffffffffu, sma, 1);
        sma += __shfl_xor_sync(0xffffffffu, sma, 2);
        smb += __shfl_xor_sync(0xffffffffu, smb, 1);
        smb += __shfl_xor_sync(0xffffffffu, smb, 2);
        float ia = 1.0f / sma, ib = 1.0f / smb;
#pragma unroll
        for (int nf = 0; nf < 8; nf++) {
            s[mf][nf][0] *= ia; s[mf][nf][1] *= ia;
            s[mf][nf][2] *= ib; s[mf][nf][3] *= ib;
        }
    }

    float o[2][4][4];
#pragma unroll
    for (int mf = 0; mf < 2; mf++)
#pragma unroll
        for (int nf = 0; nf < 4; nf++)
#pragma unroll
            for (int q = 0; q < 4; q++) o[mf][nf][q] = 0.f;

    const int v_row = (lane & 7) + ((lane >> 3) & 1) * 8;
    const int v_col = (lane >> 4) * 8;
#pragma unroll
    for (int kf = 0; kf < 4; kf++) {
        uint32_t aH[2][4], aL[2][4];
#pragma unroll
        for (int mf = 0; mf < 2; mf++) {
            split2(s[mf][2 * kf][0],     s[mf][2 * kf][1],     aH[mf][0], aL[mf][0]);
            split2(s[mf][2 * kf][2],     s[mf][2 * kf][3],     aH[mf][1], aL[mf][1]);
            split2(s[mf][2 * kf + 1][0], s[mf][2 * kf + 1][1], aH[mf][2], aL[mf][2]);
            split2(s[mf][2 * kf + 1][2], s[mf][2 * kf + 1][3], aH[mf][3], aL[mf][3]);
        }
        uint32_t bH[4][2], bL[4][2];
#pragma unroll
        for (int dh = 0; dh < 2; dh++) {
            uint32_t a = sbase + AVH +
                ((hl2 * 64 + kf * 16 + v_row) * QSTR + dh * 16 + v_col) * 2;
            ldsm4t(bH[2 * dh][0], bH[2 * dh][1],
                   bH[2 * dh + 1][0], bH[2 * dh + 1][1], a);
            ldsm4t(bL[2 * dh][0], bL[2 * dh][1],
                   bL[2 * dh + 1][0], bL[2 * dh + 1][1], a + T_SZ);
        }
#pragma unroll
        for (int mf = 0; mf < 2; mf++)
#pragma unroll
            for (int nf = 0; nf < 4; nf++) {
                MMA16816(o[mf][nf], aH[mf], bH[nf]);
                MMA16816(o[mf][nf], aH[mf], bL[nf]);
                MMA16816(o[mf][nf], aL[mf], bH[nf]);
            }
    }

    const int head = hp * 2 + hl2;
#pragma unroll
    for (int mf = 0; mf < 2; mf++) {
        int t1a = m0 + mf * 16 + rowl, t1b = t1a + 8;
#pragma unroll
        for (int nf = 0; nf < 4; nf++) {
            int gcol = head * 32 + nf * 8 + colb;
            uint32_t hi, lo;
            split2(o[mf][nf][0], o[mf][nf][1], hi, lo);
            *(uint32_t*)&g_ath[(w * WS2 + t1a) * DIM + gcol] = hi;
            *(uint32_t*)&g_atl[(w * WS2 + t1a) * DIM + gcol] = lo;
            split2(o[mf][nf][2], o[mf][nf][3], hi, lo);
            *(uint32_t*)&g_ath[(w * WS2 + t1b) * DIM + gcol] = hi;
            *(uint32_t*)&g_atl[(w * WS2 + t1b) * DIM + gcol] = lo;
        }
    }
}

// ---------------------------------------------------------------------------
extern "C" void kernel_launch(void* const* d_in, const int* in_sizes, int n_in,
                              void* d_out, int out_size)
{
    const float* x       = (const float*)d_in[0];
    const float* w_qkv   = (const float*)d_in[1];
    const float* b_qkv   = (const float*)d_in[2];
    const float* w_out   = (const float*)d_in[3];
    const float* b_out   = (const float*)d_in[4];
    const float* pos_enc = (const float*)d_in[5];
    float* out = (float*)d_out;

    cudaFuncSetAttribute(gemm_tc<0>, cudaFuncAttributeMaxDynamicSharedMemorySize, SMEM_SZ);
    cudaFuncSetAttribute(gemm_tc<1>, cudaFuncAttributeMaxDynamicSharedMemorySize, SMEM_SZ);
    cudaFuncSetAttribute(attn_mma, cudaFuncAttributeMaxDynamicSharedMemorySize, ATT_SMEM);

    __nv_bfloat16 *wqh, *wql, *woh, *wol, *ath, *atl;
    cudaGetSymbolAddress((void**)&wqh, g_wqh);
    cudaGetSymbolAddress((void**)&wql, g_wql);
    cudaGetSymbolAddress((void**)&woh, g_woh);
    cudaGetSymbolAddress((void**)&wol, g_wol);
    cudaGetSymbolAddress((void**)&ath, g_ath);
    cudaGetSymbolAddress((void**)&atl, g_atl);

    conv_split<<<(768 * DIM / 4 + 255) / 256, 256>>>(w_qkv, wqh, wql, 768 * DIM / 4);
    conv_split<<<(DIM * DIM / 4 + 255) / 256, 256>>>(w_out, woh, wol, DIM * DIM / 4);

    gemm_tc<0><<<NTOK / 64, 256, SMEM_SZ>>>(x, nullptr, nullptr, wqh, wql, b_qkv, nullptr);
    attn_mma<<<dim3(NWIN, 4), 128, ATT_SMEM>>>(pos_enc);
    gemm_tc<1><<<NTOK / 64, 256, SMEM_SZ>>>(nullptr, ath, atl, woh, wol, b_out, out);
}

// round 9
// speedup vs baseline: 1.1154x; 1.1154x over previous
#include <cuda_runtime.h>
#include <cuda_bf16.h>
#include <cstdint>

// ---------------------------------------------------------------------------
// ShiftedWindowAttention — round 9: round-7 tiles (32x32 warp tile, 2 CTAs/SM)
// with cp.async double-buffered B chunks (no register staging, no STS phase).
// ---------------------------------------------------------------------------

#define NWIN   2048
#define NTOK   131072
#define HEADS  8
#define HD     32
#define WS2    64
#define DIM    256
#define ATT_SCALE 0.17677669529663687f

// ---------------- scratch ---------------------------------------------------
__device__ __nv_bfloat16 g_wqh[768 * DIM];
__device__ __nv_bfloat16 g_wql[768 * DIM];
__device__ __nv_bfloat16 g_woh[DIM * DIM];
__device__ __nv_bfloat16 g_wol[DIM * DIM];
__device__ __nv_bfloat16 g_qh[NWIN * HEADS * WS2 * HD];
__device__ __nv_bfloat16 g_ql[NWIN * HEADS * WS2 * HD];
__device__ __nv_bfloat16 g_kh[NWIN * HEADS * WS2 * HD];
__device__ __nv_bfloat16 g_kl[NWIN * HEADS * WS2 * HD];
__device__ __nv_bfloat16 g_vh[NWIN * HEADS * WS2 * HD];
__device__ __nv_bfloat16 g_vl[NWIN * HEADS * WS2 * HD];
__device__ __nv_bfloat16 g_ath[NTOK * DIM];
__device__ __nv_bfloat16 g_atl[NTOK * DIM];

// ---------------- helpers ---------------------------------------------------
__device__ __forceinline__ uint32_t smem_u32(const void* p) {
    uint32_t a;
    asm("{ .reg .u64 t; cvta.to.shared.u64 t, %1; cvt.u32.u64 %0, t; }"
        : "=r"(a) : "l"(p));
    return a;
}
__device__ __forceinline__ void ldsm4(uint32_t& r0, uint32_t& r1,
                                      uint32_t& r2, uint32_t& r3, uint32_t a) {
    asm volatile("ldmatrix.sync.aligned.m8n8.x4.shared.b16 {%0,%1,%2,%3}, [%4];"
                 : "=r"(r0), "=r"(r1), "=r"(r2), "=r"(r3) : "r"(a));
}
__device__ __forceinline__ void ldsm4t(uint32_t& r0, uint32_t& r1,
                                       uint32_t& r2, uint32_t& r3, uint32_t a) {
    asm volatile("ldmatrix.sync.aligned.m8n8.x4.trans.shared.b16 {%0,%1,%2,%3}, [%4];"
                 : "=r"(r0), "=r"(r1), "=r"(r2), "=r"(r3) : "r"(a));
}
#define MMA16816(c, a, b)                                                  \
    asm volatile("mma.sync.aligned.m16n8k16.row.col.f32.bf16.bf16.f32 "    \
        "{%0,%1,%2,%3}, {%4,%5,%6,%7}, {%8,%9}, {%0,%1,%2,%3};"            \
        : "+f"((c)[0]), "+f"((c)[1]), "+f"((c)[2]), "+f"((c)[3])           \
        : "r"((a)[0]), "r"((a)[1]), "r"((a)[2]), "r"((a)[3]),              \
          "r"((b)[0]), "r"((b)[1]))

#define CP_ASYNC16(dst, src) \
    asm volatile("cp.async.cg.shared.global [%0], [%1], 16;" \
                 :: "r"(dst), "l"(src) : "memory")
#define CP_COMMIT() asm volatile("cp.async.commit_group;" ::: "memory")
#define CP_WAIT0()  asm volatile("cp.async.wait_group 0;" ::: "memory")

__device__ __forceinline__ void split2(float x, float y,
                                       uint32_t& hi, uint32_t& lo) {
    __nv_bfloat16 xh = __float2bfloat16_rn(x);
    __nv_bfloat16 yh = __float2bfloat16_rn(y);
    __nv_bfloat16 xl = __float2bfloat16_rn(x - __bfloat162float(xh));
    __nv_bfloat16 yl = __float2bfloat16_rn(y - __bfloat162float(yh));
    __nv_bfloat162 h2 = __halves2bfloat162(xh, yh);
    __nv_bfloat162 l2 = __halves2bfloat162(xl, yl);
    hi = *(uint32_t*)&h2;
    lo = *(uint32_t*)&l2;
}

// ---------------- index map (roll -4,-4 + window split) --------------------
__device__ __forceinline__ int src_offset(int R) {
    int w = R >> 6, t = R & 63;
    int b = w >> 6, widx = w & 63;
    int wy = widx >> 3, wx = widx & 7;
    int ty = t >> 3, tx = t & 7;
    int ys = ((wy << 3) + ty + 4) & 63;
    int xs = ((wx << 3) + tx + 4) & 63;
    return ((b << 12) + (ys << 6) + xs) * DIM;
}

// ---------------- fp32 -> bf16 hi/lo split (weights only) ------------------
__global__ __launch_bounds__(256) void conv_split(
    const float* __restrict__ src, __nv_bfloat16* __restrict__ hp,
    __nv_bfloat16* __restrict__ lp, int n4)
{
    int i = blockIdx.x * 256 + threadIdx.x;
    if (i >= n4) return;
    float4 v = ((const float4*)src)[i];
    uint32_t h0, l0, h1, l1;
    split2(v.x, v.y, h0, l0);
    split2(v.z, v.w, h1, l1);
    ((uint32_t*)hp)[2 * i + 0] = h0;
    ((uint32_t*)hp)[2 * i + 1] = h1;
    ((uint32_t*)lp)[2 * i + 0] = l0;
    ((uint32_t*)lp)[2 * i + 1] = l1;
}

// ---------------------------------------------------------------------------
// HMMA GEMM, M-tile 64 (2 CTAs/SM), warp tile 32x32 (2mf x 4nf over 64x128).
// K32 chunks, cp.async double buffer, one __syncthreads per chunk.
// MODE 0: qkv — A = fp32 x gathered + split on the fly; scatter split q/k/v.
// MODE 1: out-proj — A = g_ath/g_atl; scatter fp32 via src_offset.
// ---------------------------------------------------------------------------
#define A_STR   264
#define B_STR   40
#define A_OFF   1024
#define A_SPL   33792                      // 64*264*2
#define B_OFF   (A_OFF + 2 * A_SPL)        // 68608
#define B_SPL   10240
#define B_BUF   (2 * B_SPL)                // 20480
#define SMEM_SZ (B_OFF + 2 * B_BUF)        // 109568

template <int MODE>
__global__ __launch_bounds__(256, 2) void gemm_tc(
    const float* __restrict__ Af,
    const __nv_bfloat16* __restrict__ Ah, const __nv_bfloat16* __restrict__ Al,
    const __nv_bfloat16* __restrict__ Bh, const __nv_bfloat16* __restrict__ Bl,
    const float* __restrict__ bias, float* __restrict__ outp)
{
    constexpr int NTILES = (MODE == 0) ? 6 : 2;
    constexpr int TOTCH  = NTILES * 8;
    extern __shared__ char smem[];
    const uint32_t sbase = smem_u32(smem);
    const int tid  = threadIdx.x;
    const int wid  = tid >> 5;
    const int lane = tid & 31;
    const int bx   = blockIdx.x;
    const int m0 = (wid & 1) * 32;          // 2 M-warps
    const int n0 = (wid >> 1) * 32;         // 4 N-warps

    int* rowOff = (int*)smem;
    if (tid < 64) {
        int R = bx * 64 + tid;
        rowOff[tid] = (MODE == 0) ? src_offset(R) : R * DIM;
    }
    __syncthreads();

    // ---- A tile into SMEM (hi/lo, full K) ----
    if (MODE == 0) {
#pragma unroll
        for (int i = 0; i < 16; i++) {
            int idx = tid + i * 256;          // 4096 float4
            int u = idx & 63;
            int r = idx >> 6;
            float4 v = *(const float4*)(Af + rowOff[r] + u * 4);
            uint32_t h0, l0, h1, l1;
            split2(v.x, v.y, h0, l0);
            split2(v.z, v.w, h1, l1);
            char* base = smem + A_OFF + (r * A_STR + u * 4) * 2;
            *(uint2*)base = make_uint2(h0, h1);
            *(uint2*)(base + A_SPL) = make_uint2(l0, l1);
        }
    } else {
#pragma unroll
        for (int i = 0; i < 16; i++) {
            int idx = tid + i * 256;          // 4096 uint4
            int u  = idx & 31;
            int r  = (idx >> 5) & 63;
            int hl = idx >> 11;
            const __nv_bfloat16* s = (hl ? Al : Ah) + rowOff[r] + u * 8;
            uint4 v = *(const uint4*)s;
            *(uint4*)(smem + A_OFF + hl * A_SPL + (r * A_STR + u * 8) * 2) = v;
        }
    }

    // ---- B chunk loader via cp.async: global chunk gg -> buffer b ----
    auto loadB = [&](int gg, int b) {
        const int nb = (gg >> 3) * 128;
        const int cc = (gg & 7) * 32;
#pragma unroll
        for (int i = 0; i < 4; i++) {
            int idx = tid + i * 256;          // 1024 x 16B
            int hl = idx >> 9, r = (idx >> 2) & 127, u = idx & 3;
            const __nv_bfloat16* s = (hl ? Bl : Bh) + (nb + r) * DIM + cc + u * 8;
            uint32_t d = sbase + B_OFF + b * B_BUF +
                         hl * B_SPL + (r * B_STR + u * 8) * 2;
            CP_ASYNC16(d, s);
        }
        CP_COMMIT();
    };

    loadB(0, 0);
    CP_WAIT0();
    __syncthreads();

    const int a_row = lane & 15;
    const int a_col = (lane >> 4) * 8;
    const int b_row = (lane & 7) + ((lane >> 4) << 3);
    const int b_col = ((lane >> 3) & 1) * 8;
    const uint32_t aAddrH = sbase + A_OFF + ((m0 + a_row) * A_STR + a_col) * 2;
    const uint32_t aAddrL = aAddrH + A_SPL;

    float acc[2][4][4];
#pragma unroll
    for (int mf = 0; mf < 2; mf++)
#pragma unroll
        for (int nf = 0; nf < 4; nf++)
#pragma unroll
            for (int q = 0; q < 4; q++) acc[mf][nf][q] = 0.f;

#pragma unroll 1
    for (int g = 0; g < TOTCH; g++) {
        const int c   = g & 7;
        const int nt  = g >> 3;
        const int buf = g & 1;

        if (g + 1 < TOTCH) loadB(g + 1, (g + 1) & 1);

        // compute chunk g from buffer buf
        const uint32_t bBase = sbase + B_OFF + buf * B_BUF;
#pragma unroll
        for (int ks = 0; ks < 2; ks++) {
            const int kk = c * 32 + ks * 16;
            uint32_t ah[2][4], al[2][4], bh[4][2], bl[4][2];
#pragma unroll
            for (int mf = 0; mf < 2; mf++) {
                ldsm4(ah[mf][0], ah[mf][1], ah[mf][2], ah[mf][3],
                      aAddrH + (mf * 16 * A_STR + kk) * 2);
                ldsm4(al[mf][0], al[mf][1], al[mf][2], al[mf][3],
                      aAddrL + (mf * 16 * A_STR + kk) * 2);
            }
#pragma unroll
            for (int nf2 = 0; nf2 < 2; nf2++) {
                uint32_t ba = bBase +
                    ((n0 + nf2 * 16 + b_row) * B_STR + ks * 16 + b_col) * 2;
                ldsm4(bh[2 * nf2][0], bh[2 * nf2][1],
                      bh[2 * nf2 + 1][0], bh[2 * nf2 + 1][1], ba);
                ldsm4(bl[2 * nf2][0], bl[2 * nf2][1],
                      bl[2 * nf2 + 1][0], bl[2 * nf2 + 1][1], ba + B_SPL);
            }
#pragma unroll
            for (int mf = 0; mf < 2; mf++)
#pragma unroll
                for (int nf = 0; nf < 4; nf++)
                    MMA16816(acc[mf][nf], ah[mf], bh[nf]);
#pragma unroll
            for (int mf = 0; mf < 2; mf++)
#pragma unroll
                for (int nf = 0; nf < 4; nf++)
                    MMA16816(acc[mf][nf], ah[mf], bl[nf]);
#pragma unroll
            for (int mf = 0; mf < 2; mf++)
#pragma unroll
                for (int nf = 0; nf < 4; nf++)
                    MMA16816(acc[mf][nf], al[mf], bh[nf]);
        }

        // epilogue at end of each n-tile
        if (c == 7) {
            const int erow = lane >> 2;
            const int ecol = (lane & 3) * 2;
            if (MODE == 0) {
                const int bsel = (nt * 128 + n0) >> 8;   // uniform per warp
                __nv_bfloat16* dh = (bsel == 0) ? g_qh : (bsel == 1) ? g_kh : g_vh;
                __nv_bfloat16* dl = (bsel == 0) ? g_ql : (bsel == 1) ? g_kl : g_vl;
#pragma unroll
                for (int mf = 0; mf < 2; mf++) {
                    int R0 = bx * 64 + m0 + mf * 16 + erow;
                    int w0 = R0 >> 6, t0 = R0 & 63;
                    int R1 = R0 + 8;
                    int w1 = R1 >> 6, t1 = R1 & 63;
#pragma unroll
                    for (int nf = 0; nf < 4; nf++) {
                        int jg = nt * 128 + n0 + nf * 8 + ecol;
                        float bx0 = __ldg(&bias[jg]);
                        float bx1 = __ldg(&bias[jg + 1]);
                        int rem = jg & 255;
                        int h = rem >> 5, d = rem & 31;
                        uint32_t hi, lo;
                        int off0 = (((w0 << 3) + h) * WS2 + t0) * HD + d;
                        split2(acc[mf][nf][0] + bx0, acc[mf][nf][1] + bx1, hi, lo);
                        *(uint32_t*)&dh[off0] = hi;
                        *(uint32_t*)&dl[off0] = lo;
                        int off1 = (((w1 << 3) + h) * WS2 + t1) * HD + d;
                        split2(acc[mf][nf][2] + bx0, acc[mf][nf][3] + bx1, hi, lo);
                        *(uint32_t*)&dh[off1] = hi;
                        *(uint32_t*)&dl[off1] = lo;
                    }
                }
            } else {
#pragma unroll
                for (int mf = 0; mf < 2; mf++) {
                    int R0 = bx * 64 + m0 + mf * 16 + erow;
                    int so0 = src_offset(R0);
                    int so1 = src_offset(R0 + 8);
#pragma unroll
                    for (int nf = 0; nf < 4; nf++) {
                        int jg = nt * 128 + n0 + nf * 8 + ecol;
                        float bx0 = __ldg(&bias[jg]);
                        float bx1 = __ldg(&bias[jg + 1]);
                        *(float2*)&outp[so0 + jg] =
                            make_float2(acc[mf][nf][0] + bx0, acc[mf][nf][1] + bx1);
                        *(float2*)&outp[so1 + jg] =
                            make_float2(acc[mf][nf][2] + bx0, acc[mf][nf][3] + bx1);
                    }
                }
            }
#pragma unroll
            for (int mf = 0; mf < 2; mf++)
#pragma unroll
                for (int nf = 0; nf < 4; nf++)
#pragma unroll
                    for (int q = 0; q < 4; q++) acc[mf][nf][q] = 0.f;
        }

        CP_WAIT0();
        __syncthreads();
    }
}

// ---------------------------------------------------------------------------
// HMMA attention (unchanged from round 7).
// ---------------------------------------------------------------------------
#define QSTR 40
#define T_SZ 10240
#define AQH 0
#define AQL (1 * T_SZ)
#define AKH (2 * T_SZ)
#define AKL (3 * T_SZ)
#define AVH (4 * T_SZ)
#define AVL (5 * T_SZ)
#define APS (6 * T_SZ)
#define ARG (APS + 1800)
#define ATT_SMEM (ARG + 256)

__global__ __launch_bounds__(128) void attn_mma(const float* __restrict__ pos_enc)
{
    extern __shared__ char smem[];
    const uint32_t sbase = smem_u32(smem);
    const int w    = blockIdx.x;
    const int hp   = blockIdx.y;
    const int tid  = threadIdx.x;
    const int wid  = tid >> 5;
    const int lane = tid & 31;
    const int hl2  = wid >> 1;
    const int m0   = (wid & 1) * 32;

    {
        const __nv_bfloat16* srcs[6] = {g_qh, g_ql, g_kh, g_kl, g_vh, g_vl};
#pragma unroll
        for (int i = 0; i < 24; i++) {
            int idx = tid + i * 128;
            int u = idx & 3, r = (idx >> 2) & 63, hh = (idx >> 8) & 1, tz = idx >> 9;
            const __nv_bfloat16* s = srcs[tz] +
                ((((w << 3) + (hp << 1) + hh) * WS2 + r) * HD) + u * 8;
            uint4 v = *(const uint4*)s;
            *(uint4*)(smem + tz * T_SZ + ((hh * 64 + r) * QSTR + u * 8) * 2) = v;
        }
        float* psf = (float*)(smem + APS);
        for (int i = tid; i < 450; i += 128)
            psf[i] = pos_enc[(hp * 2) * 225 + i];
        int* rgp = (int*)(smem + ARG);
        if (tid < 64) {
            int widx = w & 63;
            int wy = widx >> 3, wx = widx & 7;
            int ry = (wy < 7) ? 0 : ((tid >> 3) < 4 ? 1 : 2);
            int rx = (wx < 7) ? 0 : ((tid & 7) < 4 ? 1 : 2);
            rgp[tid] = ry * 3 + rx;
        }
    }
    __syncthreads();

    const float* ps = (const float*)(smem + APS) + hl2 * 225;
    const int* rg = (const int*)(smem + ARG);

    float s[2][8][4];
#pragma unroll
    for (int mf = 0; mf < 2; mf++)
#pragma unroll
        for (int nf = 0; nf < 8; nf++)
#pragma unroll
            for (int q = 0; q < 4; q++) s[mf][nf][q] = 0.f;

    const int a_row = lane & 15;
    const int a_col = (lane >> 4) * 8;
    const int b_row = (lane & 7) + ((lane >> 4) << 3);
    const int b_col = ((lane >> 3) & 1) * 8;
    const uint32_t qA = sbase + AQH + ((hl2 * 64 + m0 + a_row) * QSTR + a_col) * 2;
    const uint32_t kB = sbase + AKH + ((hl2 * 64 + b_row) * QSTR + b_col) * 2;

#pragma unroll
    for (int ks = 0; ks < 2; ks++) {
        uint32_t ah[2][4], al[2][4], bh[8][2], bl[8][2];
#pragma unroll
        for (int mf = 0; mf < 2; mf++) {
            uint32_t a = qA + (mf * 16 * QSTR + ks * 16) * 2;
            ldsm4(ah[mf][0], ah[mf][1], ah[mf][2], ah[mf][3], a);
            ldsm4(al[mf][0], al[mf][1], al[mf][2], al[mf][3], a + T_SZ);
        }
#pragma unroll
        for (int nf2 = 0; nf2 < 4; nf2++) {
            uint32_t b = kB + (nf2 * 16 * QSTR + ks * 16) * 2;
            ldsm4(bh[2 * nf2][0], bh[2 * nf2][1],
                  bh[2 * nf2 + 1][0], bh[2 * nf2 + 1][1], b);
            ldsm4(bl[2 * nf2][0], bl[2 * nf2][1],
                  bl[2 * nf2 + 1][0], bl[2 * nf2 + 1][1], b + T_SZ);
        }
#pragma unroll
        for (int mf = 0; mf < 2; mf++)
#pragma unroll
            for (int nf = 0; nf < 8; nf++) {
                MMA16816(s[mf][nf], ah[mf], bh[nf]);
                MMA16816(s[mf][nf], ah[mf], bl[nf]);
                MMA16816(s[mf][nf], al[mf], bh[nf]);
            }
    }

    const int rowl = lane >> 2;
    const int colb = (lane & 3) * 2;
#pragma unroll
    for (int mf = 0; mf < 2; mf++) {
        int t1a = m0 + mf * 16 + rowl, t1b = t1a + 8;
        int y1a = t1a >> 3, x1a = t1a & 7;
        int y1b = t1b >> 3, x1b = t1b & 7;
        int rga = rg[t1a], rgb = rg[t1b];
        float mxa = -1e30f, mxb = -1e30f;
#pragma unroll
        for (int nf = 0; nf < 8; nf++)
#pragma unroll
            for (int e = 0; e < 2; e++) {
                int t2 = nf * 8 + colb + e;
                int y2 = t2 >> 3, x2 = t2 & 7;
                int rgc = rg[t2];
                float va = fmaf(s[mf][nf][e], ATT_SCALE,
                                ps[(y1a - y2 + 7) * 15 + (x1a - x2 + 7)]);
                float vb = fmaf(s[mf][nf][2 + e], ATT_SCALE,
                                ps[(y1b - y2 + 7) * 15 + (x1b - x2 + 7)]);
                if (rgc != rga) va = -1e30f;
                if (rgc != rgb) vb = -1e30f;
                s[mf][nf][e] = va;
                s[mf][nf][2 + e] = vb;
                mxa = fmaxf(mxa, va);
                mxb = fmaxf(mxb, vb);
            }
        mxa = fmaxf(mxa, __shfl_xor_sync(0xffffffffu, mxa, 1));
        mxa = fmaxf(mxa, __shfl_xor_sync(0xffffffffu, mxa, 2));
        mxb = fmaxf(mxb, __shfl_xor_sync(0xffffffffu, mxb, 1));
        mxb = fmaxf(mxb, __shfl_xor_sync(0xffffffffu, mxb, 2));
        float sma = 0.f, smb = 0.f;
#pragma unroll
        for (int nf = 0; nf < 8; nf++)
#pragma unroll
            for (int e = 0; e < 2; e++) {
                float ea = __expf(s[mf][nf][e] - mxa);
                float eb = __expf(s[mf][nf][2 + e] - mxb);
                s[mf][nf][e] = ea;
                s[mf][nf][2 + e] = eb;
                sma += ea;
                smb += eb;
            }
        sma += __shfl_xor_sync(0xffffffffu, sma, 1);
        sma += __shfl_xor_sync(0xffffffffu, sma, 2);
        smb += __shfl_xor_sync(0xffffffffu, smb, 1);
        smb += __shfl_xor_sync(0xffffffffu, smb, 2);
        float ia = 1.0f / sma, ib = 1.0f / smb;
#pragma unroll
        for (int nf = 0; nf < 8; nf++) {
            s[mf][nf][0] *= ia; s[mf][nf][1] *= ia;
            s[mf][nf][2] *= ib; s[mf][nf][3] *= ib;
        }
    }

    float o[2][4][4];
#pragma unroll
    for (int mf = 0; mf < 2; mf++)
#pragma unroll
        for (int nf = 0; nf < 4; nf++)
#pragma unroll
            for (int q = 0; q < 4; q++) o[mf][nf][q] = 0.f;

    const int v_row = (lane & 7) + ((lane >> 3) & 1) * 8;
    const int v_col = (lane >> 4) * 8;
#pragma unroll
    for (int kf = 0; kf < 4; kf++) {
        uint32_t aH[2][4], aL[2][4];
#pragma unroll
        for (int mf = 0; mf < 2; mf++) {
            split2(s[mf][2 * kf][0],     s[mf][2 * kf][1],     aH[mf][0], aL[mf][0]);
            split2(s[mf][2 * kf][2],     s[mf][2 * kf][3],     aH[mf][1], aL[mf][1]);
            split2(s[mf][2 * kf + 1][0], s[mf][2 * kf + 1][1], aH[mf][2], aL[mf][2]);
            split2(s[mf][2 * kf + 1][2], s[mf][2 * kf + 1][3], aH[mf][3], aL[mf][3]);
        }
        uint32_t bH[4][2], bL[4][2];
#pragma unroll
        for (int dh = 0; dh < 2; dh++) {
            uint32_t a = sbase + AVH +
                ((hl2 * 64 + kf * 16 + v_row) * QSTR + dh * 16 + v_col) * 2;
            ldsm4t(bH[2 * dh][0], bH[2 * dh][1],
                   bH[2 * dh + 1][0], bH[2 * dh + 1][1], a);
            ldsm4t(bL[2 * dh][0], bL[2 * dh][1],
                   bL[2 * dh + 1][0], bL[2 * dh + 1][1], a + T_SZ);
        }
#pragma unroll
        for (int mf = 0; mf < 2; mf++)
#pragma unroll
            for (int nf = 0; nf < 4; nf++) {
                MMA16816(o[mf][nf], aH[mf], bH[nf]);
                MMA16816(o[mf][nf], aH[mf], bL[nf]);
                MMA16816(o[mf][nf], aL[mf], bH[nf]);
            }
    }

    const int head = hp * 2 + hl2;
#pragma unroll
    for (int mf = 0; mf < 2; mf++) {
        int t1a = m0 + mf * 16 + rowl, t1b = t1a + 8;
#pragma unroll
        for (int nf = 0; nf < 4; nf++) {
            int gcol = head * 32 + nf * 8 + colb;
            uint32_t hi, lo;
            split2(o[mf][nf][0], o[mf][nf][1], hi, lo);
            *(uint32_t*)&g_ath[(w * WS2 + t1a) * DIM + gcol] = hi;
            *(uint32_t*)&g_atl[(w * WS2 + t1a) * DIM + gcol] = lo;
            split2(o[mf][nf][2], o[mf][nf][3], hi, lo);
            *(uint32_t*)&g_ath[(w * WS2 + t1b) * DIM + gcol] = hi;
            *(uint32_t*)&g_atl[(w * WS2 + t1b) * DIM + gcol] = lo;
        }
    }
}

// ---------------------------------------------------------------------------
extern "C" void kernel_launch(void* const* d_in, const int* in_sizes, int n_in,
                              void* d_out, int out_size)
{
    const float* x       = (const float*)d_in[0];
    const float* w_qkv   = (const float*)d_in[1];
    const float* b_qkv   = (const float*)d_in[2];
    const float* w_out   = (const float*)d_in[3];
    const float* b_out   = (const float*)d_in[4];
    const float* pos_enc = (const float*)d_in[5];
    float* out = (float*)d_out;

    cudaFuncSetAttribute(gemm_tc<0>, cudaFuncAttributeMaxDynamicSharedMemorySize, SMEM_SZ);
    cudaFuncSetAttribute(gemm_tc<1>, cudaFuncAttributeMaxDynamicSharedMemorySize, SMEM_SZ);
    cudaFuncSetAttribute(attn_mma, cudaFuncAttributeMaxDynamicSharedMemorySize, ATT_SMEM);

    __nv_bfloat16 *wqh, *wql, *woh, *wol, *ath, *atl;
    cudaGetSymbolAddress((void**)&wqh, g_wqh);
    cudaGetSymbolAddress((void**)&wql, g_wql);
    cudaGetSymbolAddress((void**)&woh, g_woh);
    cudaGetSymbolAddress((void**)&wol, g_wol);
    cudaGetSymbolAddress((void**)&ath, g_ath);
    cudaGetSymbolAddress((void**)&atl, g_atl);

    conv_split<<<(768 * DIM / 4 + 255) / 256, 256>>>(w_qkv, wqh, wql, 768 * DIM / 4);
    conv_split<<<(DIM * DIM / 4 + 255) / 256, 256>>>(w_out, woh, wol, DIM * DIM / 4);

    gemm_tc<0><<<NTOK / 64, 256, SMEM_SZ>>>(x, nullptr, nullptr, wqh, wql, b_qkv, nullptr);
    attn_mma<<<dim3(NWIN, 4), 128, ATT_SMEM>>>(pos_enc);
    gemm_tc<1><<<NTOK / 64, 256, SMEM_SZ>>>(nullptr, ath, atl, woh, wol, b_out, out);
}